// round 11
// baseline (speedup 1.0000x reference)
#include <cuda_runtime.h>

#define B_N 32768
#define D_N 1024
#define S_N 64
#define O_N 4
#define SPW 2                 // samples per group
#define NG  4                 // groups per warp
#define WPB 8                 // warps per gemm block
#define SPWARP (SPW * NG)     // 8 samples per warp
#define SPB (WPB * SPWARP)    // 64 samples per gemm block
#define HK  4                 // k-iters per half-tile
#define NBLK 128
#define TBLK 64
#define W_F4 1024             // float4 per W tile (O_N * D_N / 4)

__device__ int    g_bh[NBLK][S_N];
__device__ int    g_base[NBLK][S_N];
__device__ int    g_perm[B_N];
__device__ float4 g_Wt[S_N * W_F4];   // W transposed to [S][O][D]

// ---------------------------------------------------------------- hist + W transpose (fused, disjoint blocks)
__global__ void k_pre(const int* __restrict__ sid, const float4* __restrict__ W4) {
    if (blockIdx.x < NBLK) {
        __shared__ int h[S_N];
        int t = threadIdx.x;
        if (t < S_N) h[t] = 0;
        __syncthreads();
        int i = blockIdx.x * 256 + t;
        atomicAdd(&h[sid[i]], 1);
        __syncthreads();
        if (t < S_N) g_bh[blockIdx.x][t] = h[t];
    } else {
        float* Wt = reinterpret_cast<float*>(g_Wt);
        int b = blockIdx.x - NBLK;
#pragma unroll
        for (int j = 0; j < 4; ++j) {
            int t = b * 1024 + j * 256 + threadIdx.x;   // 0..65535 = S*D
            int s = t >> 10;
            int d = t & 1023;
            float4 w = W4[t];
            Wt[(s * 4 + 0) * D_N + d] = w.x;
            Wt[(s * 4 + 1) * D_N + d] = w.y;
            Wt[(s * 4 + 2) * D_N + d] = w.z;
            Wt[(s * 4 + 3) * D_N + d] = w.w;
        }
    }
}

// ---------------------------------------------------------------- scan
__global__ void k_scan() {
    __shared__ int cnt[S_N];
    __shared__ int off[S_N];
    int s = threadIdx.x;
    int c = 0;
#pragma unroll 8
    for (int b = 0; b < NBLK; ++b) c += g_bh[b][s];
    cnt[s] = c;
    __syncthreads();
    if (s == 0) {
        int a = 0;
        for (int j = 0; j < S_N; ++j) { off[j] = a; a += cnt[j]; }
    }
    __syncthreads();
    int run = off[s];
    for (int b = 0; b < NBLK; ++b) {
        g_base[b][s] = run;
        run += g_bh[b][s];
    }
}

// ---------------------------------------------------------------- scatter
__global__ void k_scatter(const int* __restrict__ sid) {
    __shared__ int h[S_N];
    int t = threadIdx.x;
    if (t < S_N) h[t] = 0;
    __syncthreads();
    int i = blockIdx.x * blockDim.x + t;
    int s = sid[i];
    int r = atomicAdd(&h[s], 1);
    g_perm[g_base[blockIdx.x][s] + r] = i;
}

// ---------------------------------------------------------------- helpers
__device__ __forceinline__ float4 wreduce4(float4 a) {
#pragma unroll
    for (int off = 16; off; off >>= 1) {
        a.x += __shfl_xor_sync(0xffffffffu, a.x, off);
        a.y += __shfl_xor_sync(0xffffffffu, a.y, off);
        a.z += __shfl_xor_sync(0xffffffffu, a.z, off);
        a.w += __shfl_xor_sync(0xffffffffu, a.w, off);
    }
    return a;
}

__device__ __forceinline__ void fma16(float4& acc, float4 v,
                                      float4 w0, float4 w1, float4 w2, float4 w3) {
    acc.x += v.x * w0.x + v.y * w0.y + v.z * w0.z + v.w * w0.w;
    acc.y += v.x * w1.x + v.y * w1.y + v.z * w1.z + v.w * w1.w;
    acc.z += v.x * w2.x + v.y * w2.y + v.z * w2.z + v.w * w2.w;
    acc.w += v.x * w3.x + v.y * w3.y + v.z * w3.z + v.w * w3.w;
}

// ---------------------------------------------------------------- gemm: pipelined half-tile double buffering
__global__ void __launch_bounds__(256, 2) k_gemm(
    const float* __restrict__ x,
    const int*   __restrict__ sid,
    const float* __restrict__ bias,
    float*       __restrict__ out)
{
    __shared__ float4 sW[W_F4];    // 16 KB: one subject's transposed W [O][D/4]

    int tid  = threadIdx.x;
    int warp = tid >> 5;
    int lane = tid & 31;
    int blockBase = blockIdx.x * SPB;

    int sFirst = sid[g_perm[blockBase]];
    int sLast  = sid[g_perm[blockBase + SPB - 1]];
    bool uni = (sFirst == sLast);

    if (uni) {
        const float4* wsrc = g_Wt + sFirst * W_F4;
#pragma unroll
        for (int j = 0; j < 4; ++j)
            sW[j * 256 + tid] = wsrc[j * 256 + tid];
    }
    __syncthreads();

    const float4* x4 = reinterpret_cast<const float4*>(x);
    int warpBase = blockBase + warp * SPWARP;

    if (uni) {
        float4 bb = reinterpret_cast<const float4*>(bias)[sFirst];

        int ia = g_perm[warpBase + 0];
        int ib = g_perm[warpBase + 1];
        const float4* pa = x4 + ia * (D_N / 4) + lane;
        const float4* pb = x4 + ib * (D_N / 4) + lane;

        float4 A0[HK], A1[HK], B0[HK], B1[HK];
        // prologue: H0 of group 0
#pragma unroll
        for (int k = 0; k < HK; ++k) { A0[k] = pa[k * 32]; A1[k] = pb[k * 32]; }

#pragma unroll
        for (int g = 0; g < NG; ++g) {
            // issue H1 loads for current group (independent of H0 compute)
#pragma unroll
            for (int k = 0; k < HK; ++k) { B0[k] = pa[(k + HK) * 32]; B1[k] = pb[(k + HK) * 32]; }

            float4 acc0 = {0.f, 0.f, 0.f, 0.f};
            float4 acc1 = {0.f, 0.f, 0.f, 0.f};

            // compute H0 (waits only on A-buffers)
#pragma unroll
            for (int k = 0; k < HK; ++k) {
                int dv = k * 32 + lane;
                float4 w0 = sW[0 * 256 + dv];
                float4 w1 = sW[1 * 256 + dv];
                float4 w2 = sW[2 * 256 + dv];
                float4 w3 = sW[3 * 256 + dv];
                fma16(acc0, A0[k], w0, w1, w2, w3);
                fma16(acc1, A1[k], w0, w1, w2, w3);
            }

            // issue next group's H0 loads before computing H1 -> loads never stop
            int ian = 0, ibn = 0;
            const float4 *pan = pa, *pbn = pb;
            if (g + 1 < NG) {
                ian = g_perm[warpBase + 2 * (g + 1)];
                ibn = g_perm[warpBase + 2 * (g + 1) + 1];
                pan = x4 + ian * (D_N / 4) + lane;
                pbn = x4 + ibn * (D_N / 4) + lane;
#pragma unroll
                for (int k = 0; k < HK; ++k) { A0[k] = pan[k * 32]; A1[k] = pbn[k * 32]; }
            }

            // compute H1 (waits on B-buffers, which have been in flight during H0)
#pragma unroll
            for (int k = 0; k < HK; ++k) {
                int dv = (k + HK) * 32 + lane;
                float4 w0 = sW[0 * 256 + dv];
                float4 w1 = sW[1 * 256 + dv];
                float4 w2 = sW[2 * 256 + dv];
                float4 w3 = sW[3 * 256 + dv];
                fma16(acc0, B0[k], w0, w1, w2, w3);
                fma16(acc1, B1[k], w0, w1, w2, w3);
            }

            // reduce and store this group
            acc0 = wreduce4(acc0);
            acc1 = wreduce4(acc1);
            if (lane == 0) {
                float4 r = {acc0.x + bb.x, acc0.y + bb.y, acc0.z + bb.z, acc0.w + bb.w};
                reinterpret_cast<float4*>(out)[ia] = r;
            }
            if (lane == 1) {
                float4 r = {acc1.x + bb.x, acc1.y + bb.y, acc1.z + bb.z, acc1.w + bb.w};
                reinterpret_cast<float4*>(out)[ib] = r;
            }

            if (g + 1 < NG) { ia = ian; ib = ibn; pa = pan; pb = pbn; }
        }
    } else {
        // boundary block (<=63 of 512): per-sample W from global (L2-resident)
#pragma unroll
        for (int s = 0; s < SPWARP; ++s) {
            int idx = g_perm[warpBase + s];
            int sd  = sid[idx];
            const float4* xp  = x4 + idx * (D_N / 4) + lane;
            const float4* Wt4 = g_Wt + sd * W_F4;
            float4 xv[8];
#pragma unroll
            for (int k = 0; k < 8; ++k) xv[k] = xp[k * 32];
            float4 acc = {0.f, 0.f, 0.f, 0.f};
#pragma unroll
            for (int k = 0; k < 8; ++k) {
                int dv = k * 32 + lane;
                float4 w0 = Wt4[0 * 256 + dv];
                float4 w1 = Wt4[1 * 256 + dv];
                float4 w2 = Wt4[2 * 256 + dv];
                float4 w3 = Wt4[3 * 256 + dv];
                fma16(acc, xv[k], w0, w1, w2, w3);
            }
            acc = wreduce4(acc);
            if (lane == 0) {
                float4 bb = reinterpret_cast<const float4*>(bias)[sd];
                float4 r = {acc.x + bb.x, acc.y + bb.y, acc.z + bb.z, acc.w + bb.w};
                reinterpret_cast<float4*>(out)[idx] = r;
            }
        }
    }
}

// ---------------------------------------------------------------- launch
extern "C" void kernel_launch(void* const* d_in, const int* in_sizes, int n_in,
                              void* d_out, int out_size) {
    const float* x    = (const float*)d_in[0];   // [B, D]
    const int*   sid  = (const int*)d_in[1];     // [B]
    const float* W    = (const float*)d_in[2];   // [S, D, O]
    const float* bias = (const float*)d_in[3];   // [S, O]
    float*       out  = (float*)d_out;           // [B, O]

    (void)in_sizes; (void)n_in; (void)out_size;

    k_pre<<<NBLK + TBLK, 256>>>(sid, (const float4*)W);
    k_scan<<<1, 64>>>();
    k_scatter<<<NBLK, 256>>>(sid);
    k_gemm<<<B_N / SPB, 256>>>(x, sid, bias, out);
}

// round 12
// speedup vs baseline: 1.1100x; 1.1100x over previous
#include <cuda_runtime.h>
#include <cstdint>

#define B_N 32768
#define D_N 1024
#define S_N 64
#define O_N 4
#define NG  4                  // sample-pairs per warp
#define SPWARP (2 * NG)        // 8 samples per warp
#define WPB 8
#define SPB (WPB * SPWARP)     // 64 samples per block
#define NSTAGE (NG * 8)        // 32 k-stages per warp
#define RING 4                 // ring slots (1 KB each)
#define DEPTH 3                // stages in flight
#define NBLK 128
#define TBLK 64
#define W_F4 1024              // float4 per W tile

__device__ int    g_bh[NBLK][S_N];
__device__ int    g_base[NBLK][S_N];
__device__ int    g_perm[B_N];
__device__ float4 g_Wt[S_N * W_F4];   // W transposed to [S][O][D]

// ---------------------------------------------------------------- cp.async helpers
__device__ __forceinline__ void cp16(uint32_t dst, const void* src) {
    asm volatile("cp.async.cg.shared.global [%0], [%1], 16;" :: "r"(dst), "l"(src));
}
__device__ __forceinline__ void cp_commit() {
    asm volatile("cp.async.commit_group;" ::: "memory");
}
__device__ __forceinline__ void cp_wait2() {
    asm volatile("cp.async.wait_group %0;" :: "n"(DEPTH - 1) : "memory");
}

// ---------------------------------------------------------------- hist + W transpose
__global__ void k_pre(const int* __restrict__ sid, const float4* __restrict__ W4) {
    if (blockIdx.x < NBLK) {
        __shared__ int h[S_N];
        int t = threadIdx.x;
        if (t < S_N) h[t] = 0;
        __syncthreads();
        int i = blockIdx.x * 256 + t;
        atomicAdd(&h[sid[i]], 1);
        __syncthreads();
        if (t < S_N) g_bh[blockIdx.x][t] = h[t];
    } else {
        float* Wt = reinterpret_cast<float*>(g_Wt);
        int b = blockIdx.x - NBLK;
#pragma unroll
        for (int j = 0; j < 4; ++j) {
            int t = b * 1024 + j * 256 + threadIdx.x;   // 0..65535 = S*D
            int s = t >> 10;
            int d = t & 1023;
            float4 w = W4[t];
            Wt[(s * 4 + 0) * D_N + d] = w.x;
            Wt[(s * 4 + 1) * D_N + d] = w.y;
            Wt[(s * 4 + 2) * D_N + d] = w.z;
            Wt[(s * 4 + 3) * D_N + d] = w.w;
        }
    }
}

// ---------------------------------------------------------------- scan
__global__ void k_scan() {
    __shared__ int cnt[S_N];
    __shared__ int off[S_N];
    int s = threadIdx.x;
    int c = 0;
#pragma unroll 8
    for (int b = 0; b < NBLK; ++b) c += g_bh[b][s];
    cnt[s] = c;
    __syncthreads();
    if (s == 0) {
        int a = 0;
        for (int j = 0; j < S_N; ++j) { off[j] = a; a += cnt[j]; }
    }
    __syncthreads();
    int run = off[s];
    for (int b = 0; b < NBLK; ++b) {
        g_base[b][s] = run;
        run += g_bh[b][s];
    }
}

// ---------------------------------------------------------------- scatter
__global__ void k_scatter(const int* __restrict__ sid) {
    __shared__ int h[S_N];
    int t = threadIdx.x;
    if (t < S_N) h[t] = 0;
    __syncthreads();
    int i = blockIdx.x * blockDim.x + t;
    int s = sid[i];
    int r = atomicAdd(&h[s], 1);
    g_perm[g_base[blockIdx.x][s] + r] = i;
}

// ---------------------------------------------------------------- helpers
__device__ __forceinline__ float4 wreduce4(float4 a) {
#pragma unroll
    for (int off = 16; off; off >>= 1) {
        a.x += __shfl_xor_sync(0xffffffffu, a.x, off);
        a.y += __shfl_xor_sync(0xffffffffu, a.y, off);
        a.z += __shfl_xor_sync(0xffffffffu, a.z, off);
        a.w += __shfl_xor_sync(0xffffffffu, a.w, off);
    }
    return a;
}
__device__ __forceinline__ void fma16(float4& acc, float4 v,
                                      float4 w0, float4 w1, float4 w2, float4 w3) {
    acc.x += v.x * w0.x + v.y * w0.y + v.z * w0.z + v.w * w0.w;
    acc.y += v.x * w1.x + v.y * w1.y + v.z * w1.z + v.w * w1.w;
    acc.z += v.x * w2.x + v.y * w2.y + v.z * w2.z + v.w * w2.w;
    acc.w += v.x * w3.x + v.y * w3.y + v.z * w3.z + v.w * w3.w;
}

// ---------------------------------------------------------------- gemm: warp-private cp.async stream
__global__ void __launch_bounds__(256) k_gemm(
    const float* __restrict__ x,
    const int*   __restrict__ sid,
    const float* __restrict__ bias,
    float*       __restrict__ out)
{
    __shared__ float4 sW[W_F4];                  // 16 KB
    __shared__ float4 sX[WPB * RING * 64];       // 32 KB: 4 KB ring per warp

    int tid  = threadIdx.x;
    int warp = tid >> 5;
    int lane = tid & 31;
    int blockBase = blockIdx.x * SPB;

    int sFirst = sid[g_perm[blockBase]];
    int sLast  = sid[g_perm[blockBase + SPB - 1]];
    bool uni = (sFirst == sLast);

    // per-warp sample indices (sorted, same subject when uni)
    int idxs[SPWARP];
#pragma unroll
    for (int s = 0; s < SPWARP; ++s)
        idxs[s] = g_perm[blockBase + warp * SPWARP + s];

    const float4* x4 = reinterpret_cast<const float4*>(x);
    uint32_t sxb = (uint32_t)__cvta_generic_to_shared(sX) + (uint32_t)(warp * RING * 64 * 16);

    if (uni) {
        // cooperative W tile load
        const float4* wsrc = g_Wt + sFirst * W_F4;
#pragma unroll
        for (int j = 0; j < 4; ++j)
            sW[j * 256 + tid] = wsrc[j * 256 + tid];

        // pipeline prologue: stages 0..DEPTH-1 (stage s: pair g=s>>3, k=s&7)
#pragma unroll
        for (int s = 0; s < DEPTH; ++s) {
            int g = s >> 3, k = s & 7, slot = s & (RING - 1);
            cp16(sxb + (uint32_t)((slot * 64 + lane) * 16),
                 x4 + idxs[2 * g]     * (D_N / 4) + k * 32 + lane);
            cp16(sxb + (uint32_t)((slot * 64 + 32 + lane) * 16),
                 x4 + idxs[2 * g + 1] * (D_N / 4) + k * 32 + lane);
            cp_commit();
        }
    }
    __syncthreads();   // W visible to all warps (both paths reach here)

    if (uni) {
        float4 bb = reinterpret_cast<const float4*>(bias)[sFirst];

#pragma unroll
        for (int g = 0; g < NG; ++g) {
            float4 acc0 = {0.f, 0.f, 0.f, 0.f};
            float4 acc1 = {0.f, 0.f, 0.f, 0.f};
#pragma unroll
            for (int k = 0; k < 8; ++k) {
                int s = g * 8 + k;
                int slot = s & (RING - 1);

                cp_wait2();          // stage s resident
                __syncwarp();

                float4 xa = sX[warp * (RING * 64) + slot * 64 + lane];
                float4 xb = sX[warp * (RING * 64) + slot * 64 + 32 + lane];

                // refill: issue stage s+DEPTH into the slot consumed at iter s-1
                int sn = s + DEPTH;
                if (sn < NSTAGE) {
                    int gn = sn >> 3, kn = sn & 7, sl = sn & (RING - 1);
                    cp16(sxb + (uint32_t)((sl * 64 + lane) * 16),
                         x4 + idxs[2 * gn]     * (D_N / 4) + kn * 32 + lane);
                    cp16(sxb + (uint32_t)((sl * 64 + 32 + lane) * 16),
                         x4 + idxs[2 * gn + 1] * (D_N / 4) + kn * 32 + lane);
                }
                cp_commit();         // always commit to keep group counting aligned

                int dv = k * 32 + lane;
                float4 w0 = sW[0 * 256 + dv];
                float4 w1 = sW[1 * 256 + dv];
                float4 w2 = sW[2 * 256 + dv];
                float4 w3 = sW[3 * 256 + dv];
                fma16(acc0, xa, w0, w1, w2, w3);
                fma16(acc1, xb, w0, w1, w2, w3);
            }
            // epilogue for this pair
            acc0 = wreduce4(acc0);
            acc1 = wreduce4(acc1);
            if (lane == 0) {
                float4 r = {acc0.x + bb.x, acc0.y + bb.y, acc0.z + bb.z, acc0.w + bb.w};
                reinterpret_cast<float4*>(out)[idxs[2 * g]] = r;
            }
            if (lane == 1) {
                float4 r = {acc1.x + bb.x, acc1.y + bb.y, acc1.z + bb.z, acc1.w + bb.w};
                reinterpret_cast<float4*>(out)[idxs[2 * g + 1]] = r;
            }
        }
    } else {
        // boundary block (<=63 of 512): R10-style front-batched per-sample path
#pragma unroll
        for (int s = 0; s < SPWARP; ++s) {
            int idx = idxs[s];
            int sd  = sid[idx];
            const float4* xp  = x4 + idx * (D_N / 4) + lane;
            const float4* Wt4 = g_Wt + sd * W_F4;
            float4 xv[8];
#pragma unroll
            for (int k = 0; k < 8; ++k) xv[k] = xp[k * 32];
            float4 acc = {0.f, 0.f, 0.f, 0.f};
#pragma unroll
            for (int k = 0; k < 8; ++k) {
                int dv = k * 32 + lane;
                float4 w0 = Wt4[0 * 256 + dv];
                float4 w1 = Wt4[1 * 256 + dv];
                float4 w2 = Wt4[2 * 256 + dv];
                float4 w3 = Wt4[3 * 256 + dv];
                fma16(acc, xv[k], w0, w1, w2, w3);
            }
            acc = wreduce4(acc);
            if (lane == 0) {
                float4 bb = reinterpret_cast<const float4*>(bias)[sd];
                float4 r = {acc.x + bb.x, acc.y + bb.y, acc.z + bb.z, acc.w + bb.w};
                reinterpret_cast<float4*>(out)[idx] = r;
            }
        }
    }
}

// ---------------------------------------------------------------- launch
extern "C" void kernel_launch(void* const* d_in, const int* in_sizes, int n_in,
                              void* d_out, int out_size) {
    const float* x    = (const float*)d_in[0];   // [B, D]
    const int*   sid  = (const int*)d_in[1];     // [B]
    const float* W    = (const float*)d_in[2];   // [S, D, O]
    const float* bias = (const float*)d_in[3];   // [S, O]
    float*       out  = (float*)d_out;           // [B, O]

    (void)in_sizes; (void)n_in; (void)out_size;

    k_pre<<<NBLK + TBLK, 256>>>(sid, (const float4*)W);
    k_scan<<<1, 64>>>();
    k_scatter<<<NBLK, 256>>>(sid);
    k_gemm<<<B_N / SPB, 256>>>(x, sid, bias, out);
}

// round 13
// speedup vs baseline: 1.4113x; 1.2714x over previous
#include <cuda_runtime.h>

#define B_N 32768
#define D_N 1024
#define S_N 64
#define O_N 4
#define NG  4                  // sample-pairs per warp
#define SPWARP (2 * NG)        // 8 samples per warp
#define WPB 8
#define SPB (WPB * SPWARP)     // 64 samples per block
#define HK  4                  // k-iters per half-tile
#define NBLK 128
#define TBLK 64
#define W_F4 1024              // float4 per W tile (O_N * D_N / 4)

__device__ int    g_bh[NBLK][S_N];
__device__ int    g_base[NBLK][S_N];
__device__ int    g_perm[B_N];
__device__ float4 g_Wt[S_N * W_F4];   // W transposed to [S][O][D]

// ---------------------------------------------------------------- hist + W transpose (fused, disjoint blocks)
__global__ void k_pre(const int* __restrict__ sid, const float4* __restrict__ W4) {
    if (blockIdx.x < NBLK) {
        __shared__ int h[S_N];
        int t = threadIdx.x;
        if (t < S_N) h[t] = 0;
        __syncthreads();
        int i = blockIdx.x * 256 + t;
        atomicAdd(&h[sid[i]], 1);
        __syncthreads();
        if (t < S_N) g_bh[blockIdx.x][t] = h[t];
    } else {
        float* Wt = reinterpret_cast<float*>(g_Wt);
        int b = blockIdx.x - NBLK;
#pragma unroll
        for (int j = 0; j < 4; ++j) {
            int t = b * 1024 + j * 256 + threadIdx.x;   // 0..65535 = S*D
            int s = t >> 10;
            int d = t & 1023;
            float4 w = W4[t];
            Wt[(s * 4 + 0) * D_N + d] = w.x;
            Wt[(s * 4 + 1) * D_N + d] = w.y;
            Wt[(s * 4 + 2) * D_N + d] = w.z;
            Wt[(s * 4 + 3) * D_N + d] = w.w;
        }
    }
}

// ---------------------------------------------------------------- scan
__global__ void k_scan() {
    __shared__ int cnt[S_N];
    __shared__ int off[S_N];
    int s = threadIdx.x;
    int c = 0;
#pragma unroll 8
    for (int b = 0; b < NBLK; ++b) c += g_bh[b][s];
    cnt[s] = c;
    __syncthreads();
    if (s == 0) {
        int a = 0;
        for (int j = 0; j < S_N; ++j) { off[j] = a; a += cnt[j]; }
    }
    __syncthreads();
    int run = off[s];
    for (int b = 0; b < NBLK; ++b) {
        g_base[b][s] = run;
        run += g_bh[b][s];
    }
}

// ---------------------------------------------------------------- scatter
__global__ void k_scatter(const int* __restrict__ sid) {
    __shared__ int h[S_N];
    int t = threadIdx.x;
    if (t < S_N) h[t] = 0;
    __syncthreads();
    int i = blockIdx.x * blockDim.x + t;
    int s = sid[i];
    int r = atomicAdd(&h[s], 1);
    g_perm[g_base[blockIdx.x][s] + r] = i;
}

// ---------------------------------------------------------------- helpers
__device__ __forceinline__ float dot4(float4 a, float4 w) {
    return a.x * w.x + a.y * w.y + a.z * w.z + a.w * w.w;
}
__device__ __forceinline__ float wredf(float a) {
#pragma unroll
    for (int off = 16; off; off >>= 1)
        a += __shfl_xor_sync(0xffffffffu, a, off);
    return a;
}

// ---------------------------------------------------------------- gemm: reg-dieted half-tile pipeline
__global__ void __launch_bounds__(256) k_gemm(
    const float* __restrict__ x,
    const int*   __restrict__ sid,
    const float* __restrict__ bias,
    float*       __restrict__ out)
{
    __shared__ float4 sW[W_F4];    // 16 KB: one subject's transposed W [O][D/4]

    int tid  = threadIdx.x;
    int warp = tid >> 5;
    int lane = tid & 31;
    int blockBase = blockIdx.x * SPB;

    int sFirst = sid[g_perm[blockBase]];
    int sLast  = sid[g_perm[blockBase + SPB - 1]];
    bool uni = (sFirst == sLast);

    if (uni) {
        const float4* wsrc = g_Wt + sFirst * W_F4;
#pragma unroll
        for (int j = 0; j < 4; ++j)
            sW[j * 256 + tid] = wsrc[j * 256 + tid];
    }
    __syncthreads();

    const float4* x4 = reinterpret_cast<const float4*>(x);
    int warpBase = blockBase + warp * SPWARP;

    if (uni) {
        float4 bb = reinterpret_cast<const float4*>(bias)[sFirst];

        int ia = g_perm[warpBase + 0];
        int ib = g_perm[warpBase + 1];
        const float4* pa = x4 + ia * (D_N / 4) + lane;
        const float4* pb = x4 + ib * (D_N / 4) + lane;

        float4 A0[HK], A1[HK], B0[HK], B1[HK];
        // prologue: H0 of pair 0
#pragma unroll
        for (int k = 0; k < HK; ++k) { A0[k] = pa[k * 32]; A1[k] = pb[k * 32]; }

#pragma unroll 1
        for (int g = 0; g < NG; ++g) {
            // issue H1 loads (independent of H0 compute)
#pragma unroll
            for (int k = 0; k < HK; ++k) { B0[k] = pa[(k + HK) * 32]; B1[k] = pb[(k + HK) * 32]; }

            float acc0[O_N] = {0.f, 0.f, 0.f, 0.f};
            float acc1[O_N] = {0.f, 0.f, 0.f, 0.f};

            // compute H0 — one W float4 live at a time
#pragma unroll
            for (int k = 0; k < HK; ++k) {
                int dv = k * 32 + lane;
#pragma unroll
                for (int o = 0; o < O_N; ++o) {
                    float4 w = sW[o * 256 + dv];
                    acc0[o] += dot4(A0[k], w);
                    acc1[o] += dot4(A1[k], w);
                }
            }

            // issue next pair's H0 loads before computing H1 -> loads never stop
            int ian = ia, ibn = ib;
            const float4 *pan = pa, *pbn = pb;
            if (g + 1 < NG) {
                ian = g_perm[warpBase + 2 * (g + 1)];
                ibn = g_perm[warpBase + 2 * (g + 1) + 1];
                pan = x4 + ian * (D_N / 4) + lane;
                pbn = x4 + ibn * (D_N / 4) + lane;
#pragma unroll
                for (int k = 0; k < HK; ++k) { A0[k] = pan[k * 32]; A1[k] = pbn[k * 32]; }
            }

            // compute H1 (B-buffers arrived during H0 compute)
#pragma unroll
            for (int k = 0; k < HK; ++k) {
                int dv = (k + HK) * 32 + lane;
#pragma unroll
                for (int o = 0; o < O_N; ++o) {
                    float4 w = sW[o * 256 + dv];
                    acc0[o] += dot4(B0[k], w);
                    acc1[o] += dot4(B1[k], w);
                }
            }

            // reduce and store this pair
#pragma unroll
            for (int o = 0; o < O_N; ++o) { acc0[o] = wredf(acc0[o]); acc1[o] = wredf(acc1[o]); }
            if (lane == 0) {
                float4 r = {acc0[0] + bb.x, acc0[1] + bb.y, acc0[2] + bb.z, acc0[3] + bb.w};
                reinterpret_cast<float4*>(out)[ia] = r;
            }
            if (lane == 1) {
                float4 r = {acc1[0] + bb.x, acc1[1] + bb.y, acc1[2] + bb.z, acc1[3] + bb.w};
                reinterpret_cast<float4*>(out)[ib] = r;
            }

            ia = ian; ib = ibn; pa = pan; pb = pbn;
        }
    } else {
        // boundary block (<=63 of 512): front-batched per-sample path (W via L2)
#pragma unroll 1
        for (int s = 0; s < SPWARP; ++s) {
            int idx = g_perm[warpBase + s];
            int sd  = sid[idx];
            const float4* xp  = x4 + idx * (D_N / 4) + lane;
            const float4* Wt4 = g_Wt + sd * W_F4;
            float4 xv[8];
#pragma unroll
            for (int k = 0; k < 8; ++k) xv[k] = xp[k * 32];
            float acc[O_N] = {0.f, 0.f, 0.f, 0.f};
#pragma unroll
            for (int k = 0; k < 8; ++k) {
                int dv = k * 32 + lane;
#pragma unroll
                for (int o = 0; o < O_N; ++o) {
                    float4 w = Wt4[o * 256 + dv];
                    acc[o] += dot4(xv[k], w);
                }
            }
#pragma unroll
            for (int o = 0; o < O_N; ++o) acc[o] = wredf(acc[o]);
            if (lane == 0) {
                float4 bbl = reinterpret_cast<const float4*>(bias)[sd];
                float4 r = {acc[0] + bbl.x, acc[1] + bbl.y, acc[2] + bbl.z, acc[3] + bbl.w};
                reinterpret_cast<float4*>(out)[idx] = r;
            }
        }
    }
}

// ---------------------------------------------------------------- launch
extern "C" void kernel_launch(void* const* d_in, const int* in_sizes, int n_in,
                              void* d_out, int out_size) {
    const float* x    = (const float*)d_in[0];   // [B, D]
    const int*   sid  = (const int*)d_in[1];     // [B]
    const float* W    = (const float*)d_in[2];   // [S, D, O]
    const float* bias = (const float*)d_in[3];   // [S, O]
    float*       out  = (float*)d_out;           // [B, O]

    (void)in_sizes; (void)n_in; (void)out_size;

    k_pre<<<NBLK + TBLK, 256>>>(sid, (const float4*)W);
    k_scan<<<1, 64>>>();
    k_scatter<<<NBLK, 256>>>(sid);
    k_gemm<<<B_N / SPB, 256>>>(x, sid, bias, out);
}

// round 16
// speedup vs baseline: 1.9245x; 1.3636x over previous
#include <cuda_runtime.h>

#define B_N 32768
#define D_N 1024
#define S_N 64
#define O_N 4
#define SPW 2            // samples per warp in gemm
#define WPB 8            // warps per gemm block
#define SPB (SPW * WPB)  // 16 samples per gemm block
#define NBLK 128         // sort blocks (256 threads each)
#define TBLK 64          // transpose blocks appended to the same grid
#define W_F4 1024        // float4 per W tile (O_N * D_N / 4)

__device__ int    g_counts[S_N];
__device__ int    g_claim[S_N];
__device__ int    g_cin;
__device__ int    g_cdone;
__device__ int    g_perm[B_N];
__device__ float4 g_Wt[S_N * W_F4];   // W transposed to [S][O][D] (1 MB scratch)

// ---------------------------------------------------------------- fused sort (hist+scan+scatter) + W transpose
// Blocks [0, NBLK): counting sort with an internal device-wide barrier.
// Blocks [NBLK, NBLK+TBLK): W transpose (no barrier participation).
// All 192 blocks are co-resident in wave 1 (256 thr, low regs), so the
// spin cannot deadlock. The last block resets all counters to zero, so
// every graph replay starts from the same state (deterministic).
__global__ void k_sort(const int* __restrict__ sid, const float4* __restrict__ W4) {
    if (blockIdx.x >= NBLK) {
        // ---- transpose part: W[s][d][o] (float4 per d) -> Wt[s][o][d]
        float* Wt = reinterpret_cast<float*>(g_Wt);
        int b = blockIdx.x - NBLK;
#pragma unroll
        for (int j = 0; j < 4; ++j) {
            int t = b * 1024 + j * 256 + threadIdx.x;   // 0..65535 = S*D
            int s = t >> 10;
            int d = t & 1023;
            float4 w = W4[t];
            Wt[(s * 4 + 0) * D_N + d] = w.x;
            Wt[(s * 4 + 1) * D_N + d] = w.y;
            Wt[(s * 4 + 2) * D_N + d] = w.z;
            Wt[(s * 4 + 3) * D_N + d] = w.w;
        }
        return;
    }

    __shared__ int h[S_N];
    __shared__ int off[S_N];
    __shared__ int base[S_N];
    int t = threadIdx.x;

    // ---- phase 1: local histogram + global accumulate
    if (t < S_N) h[t] = 0;
    __syncthreads();
    int i = blockIdx.x * 256 + t;
    int s = sid[i];
    int r = atomicAdd(&h[s], 1);
    __syncthreads();
    if (t < S_N && h[t] > 0) atomicAdd(&g_counts[t], h[t]);
    __threadfence();
    __syncthreads();

    // ---- device-wide barrier
    if (t == 0) {
        atomicAdd(&g_cin, 1);
        while (atomicAdd(&g_cin, 0) < NBLK) { }
    }
    __syncthreads();
    __threadfence();

    // ---- phase 2: each block computes the subject prefix locally (64 adds)
    if (t == 0) {
        int a = 0;
        for (int j = 0; j < S_N; ++j) { off[j] = a; a += g_counts[j]; }
    }
    __syncthreads();

    // claim this block's slots per subject (order across blocks irrelevant)
    if (t < S_N) base[t] = (h[t] > 0) ? off[t] + atomicAdd(&g_claim[t], h[t]) : 0;
    __syncthreads();

    // ---- phase 3: scatter
    g_perm[base[s] + r] = i;
    __threadfence();
    __syncthreads();

    // ---- cleanup: last block resets counters for the next replay
    if (t == 0) {
        int d = atomicAdd(&g_cdone, 1);
        if (d == NBLK - 1) {
            for (int j = 0; j < S_N; ++j) { g_counts[j] = 0; g_claim[j] = 0; }
            g_cin = 0;
            g_cdone = 0;
        }
    }
}

// ---------------------------------------------------------------- helpers
__device__ __forceinline__ float4 wreduce4(float4 a) {
#pragma unroll
    for (int off = 16; off; off >>= 1) {
        a.x += __shfl_xor_sync(0xffffffffu, a.x, off);
        a.y += __shfl_xor_sync(0xffffffffu, a.y, off);
        a.z += __shfl_xor_sync(0xffffffffu, a.z, off);
        a.w += __shfl_xor_sync(0xffffffffu, a.w, off);
    }
    return a;
}
__device__ __forceinline__ void fma16(float4& acc, float4 v,
                                      float4 w0, float4 w1, float4 w2, float4 w3) {
    acc.x += v.x * w0.x + v.y * w0.y + v.z * w0.z + v.w * w0.w;
    acc.y += v.x * w1.x + v.y * w1.y + v.z * w1.z + v.w * w1.w;
    acc.z += v.x * w2.x + v.y * w2.y + v.z * w2.z + v.w * w2.w;
    acc.w += v.x * w3.x + v.y * w3.y + v.z * w3.z + v.w * w3.w;
}

// ---------------------------------------------------------------- gemm: full x preload (16 LDG.128/warp), smem W  [R10, unchanged]
__global__ void __launch_bounds__(256) k_gemm(
    const float* __restrict__ x,
    const int*   __restrict__ sid,
    const float* __restrict__ bias,
    float*       __restrict__ out)
{
    __shared__ float4 sW[W_F4];    // 16 KB: one subject's transposed W [O][D/4]

    int tid  = threadIdx.x;
    int warp = tid >> 5;
    int lane = tid & 31;
    int blockBase = blockIdx.x * SPB;

    int sFirst = sid[g_perm[blockBase]];
    int sLast  = sid[g_perm[blockBase + SPB - 1]];
    bool uni = (sFirst == sLast);

    int idx[SPW], sd[SPW];
#pragma unroll
    for (int s = 0; s < SPW; ++s) {
        idx[s] = g_perm[blockBase + warp * SPW + s];
        sd[s]  = sid[idx[s]];
    }

    const float4* x4 = reinterpret_cast<const float4*>(x);

    // ---- front-batched x preload: 16 independent LDG.128 = 8 KB in flight per warp
    float4 xv[SPW][8];
#pragma unroll
    for (int s = 0; s < SPW; ++s) {
        const float4* xp = x4 + idx[s] * (D_N / 4) + lane;
#pragma unroll
        for (int k = 0; k < 8; ++k)
            xv[s][k] = xp[k * 32];
    }

    // ---- cooperative W tile load (overlaps with x-load latency)
    if (uni) {
        const float4* wsrc = g_Wt + sFirst * W_F4;
#pragma unroll
        for (int j = 0; j < 4; ++j)
            sW[j * 256 + tid] = wsrc[j * 256 + tid];
    }
    __syncthreads();

    float4 acc[SPW];
#pragma unroll
    for (int s = 0; s < SPW; ++s) acc[s] = make_float4(0.f, 0.f, 0.f, 0.f);

    if (uni) {
#pragma unroll
        for (int k = 0; k < 8; ++k) {
            int dv = k * 32 + lane;
            float4 w0 = sW[0 * 256 + dv];
            float4 w1 = sW[1 * 256 + dv];
            float4 w2 = sW[2 * 256 + dv];
            float4 w3 = sW[3 * 256 + dv];
#pragma unroll
            for (int s = 0; s < SPW; ++s)
                fma16(acc[s], xv[s][k], w0, w1, w2, w3);
        }
    } else {
        // boundary block (<=63 of 2048): per-sample W from global (L2-resident)
#pragma unroll
        for (int s = 0; s < SPW; ++s) {
            const float4* Wt4 = g_Wt + sd[s] * W_F4;
#pragma unroll
            for (int k = 0; k < 8; ++k) {
                int dv = k * 32 + lane;
                float4 w0 = Wt4[0 * 256 + dv];
                float4 w1 = Wt4[1 * 256 + dv];
                float4 w2 = Wt4[2 * 256 + dv];
                float4 w3 = Wt4[3 * 256 + dv];
                fma16(acc[s], xv[s][k], w0, w1, w2, w3);
            }
        }
    }

    // ---- warp butterfly reduction
#pragma unroll
    for (int s = 0; s < SPW; ++s) acc[s] = wreduce4(acc[s]);

    // ---- lane s writes sample s
    if (lane < SPW) {
        int s = lane;
        float4 bb = reinterpret_cast<const float4*>(bias)[sd[s]];
        float4 r;
        r.x = acc[s].x + bb.x;
        r.y = acc[s].y + bb.y;
        r.z = acc[s].z + bb.z;
        r.w = acc[s].w + bb.w;
        reinterpret_cast<float4*>(out)[idx[s]] = r;
    }
}

// ---------------------------------------------------------------- launch
extern "C" void kernel_launch(void* const* d_in, const int* in_sizes, int n_in,
                              void* d_out, int out_size) {
    const float* x    = (const float*)d_in[0];   // [B, D]
    const int*   sid  = (const int*)d_in[1];     // [B]
    const float* W    = (const float*)d_in[2];   // [S, D, O]
    const float* bias = (const float*)d_in[3];   // [S, O]
    float*       out  = (float*)d_out;           // [B, O]

    (void)in_sizes; (void)n_in; (void)out_size;

    k_sort<<<NBLK + TBLK, 256>>>(sid, (const float4*)W);
    k_gemm<<<B_N / SPB, 256>>>(x, sid, bias, out);
}